// round 1
// baseline (speedup 1.0000x reference)
#include <cuda_runtime.h>

#define NG   64
#define NA   32
#define NN   2048
#define HID  128
#define FEAT 64

// scratch (static device globals — no runtime allocation)
__device__ __align__(16) float g_qkv[NN * 384];
__device__ __align__(16) float g_vals[NN * HID];

// ---------------------------------------------------------------------------
// K_qkv: g_qkv[row, 0:384] = (h ⊙ emb[graph]) @ W_qkv^T + b_qkv
// emb folded into W columns: (h⊙e) W^T == h (W⊙e)^T
// grid (6 col-slices, 64 graphs), 128 threads.
// Each thread: 1 output col × 16 rows, K unrolled by float4.
// ---------------------------------------------------------------------------
__global__ void k_qkv(const float* __restrict__ h,
                      const float* __restrict__ next_type,
                      const float* __restrict__ W_emb,
                      const float* __restrict__ W_qkv,
                      const float* __restrict__ b_qkv) {
    __shared__ float nt[FEAT];
    __shared__ float emb[HID];
    __shared__ float Wsh[64 * 132];   // padded stride 132 -> conflict-free LDS.128

    const int g = blockIdx.y, s = blockIdx.x, tid = threadIdx.x;
    if (tid < FEAT) nt[tid] = next_type[g * FEAT + tid];
    __syncthreads();
    {   // emb[f] = sum_t nt[t] * W_emb[f, t]
        float e = 0.f;
        const float* we = &W_emb[tid * FEAT];
#pragma unroll
        for (int t = 0; t < FEAT; t++) e = fmaf(nt[t], we[t], e);
        emb[tid] = e;
    }
    __syncthreads();

    const int gc0 = s * 64;
    for (int idx = tid; idx < 64 * HID; idx += 128) {
        int c = idx >> 7, k = idx & 127;
        Wsh[c * 132 + k] = W_qkv[(gc0 + c) * HID + k] * emb[k];
    }
    __syncthreads();

    const int c = tid & 63, half = tid >> 6;
    const int row0 = g * NA + half * 16;
    float acc[16];
#pragma unroll
    for (int r = 0; r < 16; r++) acc[r] = 0.f;

    const float4* h4 = (const float4*)h;
    for (int k4 = 0; k4 < 32; k4++) {
        float4 w = *(const float4*)&Wsh[c * 132 + k4 * 4];
#pragma unroll
        for (int r = 0; r < 16; r++) {
            float4 x = __ldg(&h4[(row0 + r) * 32 + k4]);
            acc[r] = fmaf(x.x, w.x, fmaf(x.y, w.y, fmaf(x.z, w.z, fmaf(x.w, w.w, acc[r]))));
        }
    }
    const int gc = gc0 + c;
    const float b = b_qkv[gc];
#pragma unroll
    for (int r = 0; r < 16; r++)
        g_qkv[(row0 + r) * 384 + gc] = acc[r] + b;
}

// ---------------------------------------------------------------------------
// K_attn: per-graph 32x32 attention.
// logits = (q·k^T)/sqrt(32) + t(d)   [b_bias cancels in softmax — dropped]
// t(d) = sum_k W_t[k] * exp(-10 (d - c_k)^2) + b_t
// vals = (softmax(logits) @ v) * sigmoid(x·W_g + b_g) + x
// grid 64, 128 threads, dynamic smem.
// ---------------------------------------------------------------------------
__global__ void k_attn(const float* __restrict__ h,
                       const float* __restrict__ pos,
                       const float* __restrict__ next_type,
                       const float* __restrict__ W_emb,
                       const float* __restrict__ W_g,
                       const float* __restrict__ b_g,
                       const float* __restrict__ W_t,
                       const float* __restrict__ b_t) {
    extern __shared__ float sm[];
    float* xs  = sm;                 // 32*132
    float* qs  = xs + 32 * 132;      // 32*132
    float* ks  = qs + 32 * 132;      // 32*132
    float* vs  = ks + 32 * 132;      // 32*132
    float* att = vs + 32 * 132;      // 32*33
    float* px  = att + 32 * 33;      // 32
    float* py  = px + 32;            // 32
    float* pz  = py + 32;            // 32
    float* gs  = pz + 32;            // 32
    float* wt  = gs + 32;            // 32
    float* nt  = wt + 32;            // 64
    float* emb = nt + 64;            // 128

    const int g = blockIdx.x, tid = threadIdx.x;
    if (tid < FEAT) nt[tid] = next_type[g * FEAT + tid];
    if (tid < 32)   wt[tid] = W_t[tid];
    if (tid >= 64 && tid < 96) {
        int i = tid - 64;
        px[i] = pos[(g * NA + i) * 3 + 0];
        py[i] = pos[(g * NA + i) * 3 + 1];
        pz[i] = pos[(g * NA + i) * 3 + 2];
    }
    __syncthreads();
    {
        float e = 0.f;
        const float* we = &W_emb[tid * FEAT];
#pragma unroll
        for (int t = 0; t < FEAT; t++) e = fmaf(nt[t], we[t], e);
        emb[tid] = e;
    }
    __syncthreads();

    // xs = h * emb (thread = feature)
    for (int i = 0; i < NA; i++)
        xs[i * 132 + tid] = h[(g * NA + i) * HID + tid] * emb[tid];

    // load q/k/v slices from g_qkv
    const float4* q4 = (const float4*)g_qkv;
    for (int idx = tid; idx < NA * 96; idx += 128) {
        int row = idx / 96, c4 = idx - row * 96;
        float4 v = q4[(g * NA + row) * 96 + c4];
        int c = c4 * 4;
        float* dst = (c < 128) ? &qs[row * 132 + c]
                   : (c < 256) ? &ks[row * 132 + c - 128]
                               : &vs[row * 132 + c - 256];
        *(float4*)dst = v;
    }
    __syncthreads();

    // gate: 4 threads per row, shfl-combine
    {
        int i = tid >> 2, part = tid & 3;
        float a = 0.f;
#pragma unroll
        for (int t = 0; t < 32; t++) {
            int k = part * 32 + t;
            a = fmaf(xs[i * 132 + k], __ldg(&W_g[k]), a);
        }
        a += __shfl_xor_sync(0xffffffffu, a, 1);
        a += __shfl_xor_sync(0xffffffffu, a, 2);
        if (part == 0) gs[i] = 1.f / (1.f + __expf(-(a + b_g[0])));
    }

    // logits: 8 pairs/thread; warp lanes share i, j = lane
    const float RS = 0.17677669529663688f;   // 1/sqrt(32)
    const float bt0 = b_t[0];
    for (int m = 0; m < 8; m++) {
        int p = tid + 128 * m;
        int i = p >> 5, j = p & 31;
        float dx = px[i] - px[j], dy = py[i] - py[j], dz = pz[i] - pz[j];
        float sq = dx * dx + dy * dy + dz * dz;
        float d  = sqrtf(fmaxf(sq, 1e-12f));
        float t  = bt0;
#pragma unroll
        for (int kk = 0; kk < 32; kk++) {
            float u = d - kk * (10.f / 31.f);
            t = fmaf(wt[kk], __expf(-10.f * u * u), t);
        }
        float acc = 0.f;
        const float4* qq = (const float4*)&qs[i * 132];
        const float4* kp = (const float4*)&ks[j * 132];
#pragma unroll 8
        for (int k4 = 0; k4 < 32; k4++) {
            float4 a = qq[k4], b = kp[k4];
            acc = fmaf(a.x, b.x, fmaf(a.y, b.y, fmaf(a.z, b.z, fmaf(a.w, b.w, acc))));
        }
        att[i * 33 + j] = acc * RS + t;
    }
    __syncthreads();

    // softmax: 4 warps × 8 rows
    {
        int w = tid >> 5, lane = tid & 31;
        for (int rr = 0; rr < 8; rr++) {
            int r = w * 8 + rr;
            float v = att[r * 33 + lane];
            float mx = v;
#pragma unroll
            for (int o = 16; o > 0; o >>= 1) mx = fmaxf(mx, __shfl_xor_sync(0xffffffffu, mx, o));
            float e = __expf(v - mx);
            float ss = e;
#pragma unroll
            for (int o = 16; o > 0; o >>= 1) ss += __shfl_xor_sync(0xffffffffu, ss, o);
            att[r * 33 + lane] = e / ss;
        }
    }
    __syncthreads();

    // out: thread = feature f, all 32 rows in registers
    float acc[NA];
#pragma unroll
    for (int i = 0; i < NA; i++) acc[i] = 0.f;
    const int f = tid;
    for (int j = 0; j < NA; j++) {
        float vj = vs[j * 132 + f];
#pragma unroll
        for (int i = 0; i < NA; i++)
            acc[i] = fmaf(att[i * 33 + j], vj, acc[i]);
    }
    for (int i = 0; i < NA; i++)
        g_vals[(g * NA + i) * HID + f] = fmaf(acc[i], gs[i], xs[i * 132 + f]);
}

// ---------------------------------------------------------------------------
// K_dense: 128 -> SiLU 106 -> SiLU 85 -> 64 -> log_softmax
// grid 128 (16 rows each), 256 threads, all weights staged in smem.
// ---------------------------------------------------------------------------
__global__ void k_dense(const float* __restrict__ W_d0, const float* __restrict__ b_d0,
                        const float* __restrict__ W_d1, const float* __restrict__ b_d1,
                        const float* __restrict__ W_d2, const float* __restrict__ b_d2,
                        float* __restrict__ out) {
    extern __shared__ float sm[];
    float* W0 = sm;                  // 106*132
    float* W1 = W0 + 106 * 132;      // 85*108
    float* W2 = W1 + 85 * 108;       // 64*88
    float* y0 = W2 + 64 * 88;        // 16*108
    float* y1 = y0 + 16 * 108;       // 16*88
    float* y2 = y1 + 16 * 88;        // 16*66

    const int tid  = threadIdx.x;
    const int row0 = blockIdx.x * 16;

    for (int idx = tid; idx < 106 * 128; idx += 256) {
        int c = idx >> 7, k = idx & 127;
        W0[c * 132 + k] = W_d0[idx];
    }
    for (int idx = tid; idx < 85 * 106; idx += 256) {
        int c = idx / 106, k = idx - c * 106;
        W1[c * 108 + k] = W_d1[idx];
    }
    for (int idx = tid; idx < 64 * 85; idx += 256) {
        int c = idx / 85, k = idx - c * 85;
        W2[c * 88 + k] = W_d2[idx];
    }
    __syncthreads();

    // layer 0: K=128
    {
        int c = tid & 127, rg = tid >> 7;
        if (c < 106) {
            float acc[8];
#pragma unroll
            for (int r = 0; r < 8; r++) acc[r] = 0.f;
            const float4* v4 = (const float4*)g_vals;
            for (int k4 = 0; k4 < 32; k4++) {
                float4 w = *(const float4*)&W0[c * 132 + k4 * 4];
#pragma unroll
                for (int r = 0; r < 8; r++) {
                    float4 x = __ldg(&v4[(row0 + rg * 8 + r) * 32 + k4]);
                    acc[r] = fmaf(x.x, w.x, fmaf(x.y, w.y, fmaf(x.z, w.z, fmaf(x.w, w.w, acc[r]))));
                }
            }
            float b = b_d0[c];
#pragma unroll
            for (int r = 0; r < 8; r++) {
                float z = acc[r] + b;
                y0[(rg * 8 + r) * 108 + c] = z / (1.f + __expf(-z));
            }
        }
    }
    __syncthreads();

    // layer 1: K=106
    {
        int c = tid & 127, rg = tid >> 7;
        if (c < 85) {
            float acc[8];
#pragma unroll
            for (int r = 0; r < 8; r++) acc[r] = 0.f;
            for (int k4 = 0; k4 < 26; k4++) {
                float4 w = *(const float4*)&W1[c * 108 + k4 * 4];
#pragma unroll
                for (int r = 0; r < 8; r++) {
                    float4 x = *(const float4*)&y0[(rg * 8 + r) * 108 + k4 * 4];
                    acc[r] = fmaf(x.x, w.x, fmaf(x.y, w.y, fmaf(x.z, w.z, fmaf(x.w, w.w, acc[r]))));
                }
            }
#pragma unroll
            for (int k = 104; k < 106; k++) {
                float w = W1[c * 108 + k];
#pragma unroll
                for (int r = 0; r < 8; r++)
                    acc[r] = fmaf(y0[(rg * 8 + r) * 108 + k], w, acc[r]);
            }
            float b = b_d1[c];
#pragma unroll
            for (int r = 0; r < 8; r++) {
                float z = acc[r] + b;
                y1[(rg * 8 + r) * 88 + c] = z / (1.f + __expf(-z));
            }
        }
    }
    __syncthreads();

    // layer 2: K=85, 64 outputs
    {
        int c = tid & 63, rg = tid >> 6;
        float acc[4];
#pragma unroll
        for (int r = 0; r < 4; r++) acc[r] = 0.f;
        for (int k4 = 0; k4 < 21; k4++) {
            float4 w = *(const float4*)&W2[c * 88 + k4 * 4];
#pragma unroll
            for (int r = 0; r < 4; r++) {
                float4 x = *(const float4*)&y1[(rg * 4 + r) * 88 + k4 * 4];
                acc[r] = fmaf(x.x, w.x, fmaf(x.y, w.y, fmaf(x.z, w.z, fmaf(x.w, w.w, acc[r]))));
            }
        }
        {
            float w = W2[c * 88 + 84];
#pragma unroll
            for (int r = 0; r < 4; r++)
                acc[r] = fmaf(y1[(rg * 4 + r) * 88 + 84], w, acc[r]);
        }
        float b = b_d2[c];
#pragma unroll
        for (int r = 0; r < 4; r++)
            y2[(rg * 4 + r) * 66 + c] = acc[r] + b;
    }
    __syncthreads();

    // log_softmax over 64: 8 warps × 2 rows
    {
        int w = tid >> 5, lane = tid & 31;
        for (int rr = 0; rr < 2; rr++) {
            int r = w * 2 + rr;
            float e0 = y2[r * 66 + lane], e1 = y2[r * 66 + lane + 32];
            float mx = fmaxf(e0, e1);
#pragma unroll
            for (int o = 16; o > 0; o >>= 1) mx = fmaxf(mx, __shfl_xor_sync(0xffffffffu, mx, o));
            float s = __expf(e0 - mx) + __expf(e1 - mx);
#pragma unroll
            for (int o = 16; o > 0; o >>= 1) s += __shfl_xor_sync(0xffffffffu, s, o);
            float l = mx + __logf(s);
            out[(row0 + r) * 64 + lane]      = e0 - l;
            out[(row0 + r) * 64 + lane + 32] = e1 - l;
        }
    }
}

// ---------------------------------------------------------------------------
extern "C" void kernel_launch(void* const* d_in, const int* in_sizes, int n_in,
                              void* d_out, int out_size) {
    const float* h         = (const float*)d_in[0];
    const float* pos       = (const float*)d_in[1];
    const float* next_type = (const float*)d_in[2];
    // d_in[3] = batch (int32) — structure is fixed (arange//32), unused
    const float* W_emb = (const float*)d_in[4];
    const float* W_qkv = (const float*)d_in[5];
    const float* b_qkv = (const float*)d_in[6];
    // d_in[7] W_b, d_in[8] b_b — per-row bias cancels inside softmax, unused
    const float* W_g  = (const float*)d_in[9];
    const float* b_g  = (const float*)d_in[10];
    const float* W_t  = (const float*)d_in[11];
    const float* b_t  = (const float*)d_in[12];
    const float* W_d0 = (const float*)d_in[13];
    const float* b_d0 = (const float*)d_in[14];
    const float* W_d1 = (const float*)d_in[15];
    const float* b_d1 = (const float*)d_in[16];
    const float* W_d2 = (const float*)d_in[17];
    const float* b_d2 = (const float*)d_in[18];
    float* out = (float*)d_out;

    const int smem_attn  = 18304 * 4;   // 73216 B
    const int smem_dense = 32996 * 4;   // 131984 B
    cudaFuncSetAttribute(k_attn,  cudaFuncAttributeMaxDynamicSharedMemorySize, smem_attn);
    cudaFuncSetAttribute(k_dense, cudaFuncAttributeMaxDynamicSharedMemorySize, smem_dense);

    k_qkv<<<dim3(6, 64), 128>>>(h, next_type, W_emb, W_qkv, b_qkv);
    k_attn<<<64, 128, smem_attn>>>(h, pos, next_type, W_emb, W_g, b_g, W_t, b_t);
    k_dense<<<128, 256, smem_dense>>>(W_d0, b_d0, W_d1, b_d1, W_d2, b_d2, out);
}

// round 2
// speedup vs baseline: 1.2138x; 1.2138x over previous
#include <cuda_runtime.h>

#define NG   64
#define NA   32
#define NN   2048
#define HID  128
#define FEAT 64

// scratch (static device globals — no runtime allocation)
__device__ __align__(16) float g_qkv[NN * 384];
__device__ __align__(16) float g_vals[NN * HID];

// packed f32x2 FMA: acc.{lo,hi} += a.{lo,hi} * b.{lo,hi}
__device__ __forceinline__ void fma2(unsigned long long& acc,
                                     unsigned long long a,
                                     unsigned long long b) {
    asm("fma.rn.f32x2 %0, %1, %2, %0;" : "+l"(acc) : "l"(a), "l"(b));
}
__device__ __forceinline__ float hsum2(unsigned long long a) {
    float lo = __uint_as_float((unsigned)(a & 0xffffffffull));
    float hi = __uint_as_float((unsigned)(a >> 32));
    return lo + hi;
}

// ---------------------------------------------------------------------------
// K_qkv: g_qkv[row, 0:384] = (h ⊙ emb[graph]) @ W_qkv^T + b_qkv
// emb folded into W columns.  grid (6 col-slices, 64 graphs), 128 threads.
// h tile + W slice staged in smem; 4 rows x 4 cols register tile per thread;
// k packed in f32x2 pairs straight from LDS.128.
// ---------------------------------------------------------------------------
__global__ void k_qkv(const float* __restrict__ h,
                      const float* __restrict__ next_type,
                      const float* __restrict__ W_emb,
                      const float* __restrict__ W_qkv,
                      const float* __restrict__ b_qkv) {
    __shared__ float nt[FEAT];
    __shared__ float emb[HID];
    __shared__ float hs[32 * 132];
    __shared__ float Wsh[64 * 132];

    const int g = blockIdx.y, s = blockIdx.x, tid = threadIdx.x;
    if (tid < FEAT) nt[tid] = next_type[g * FEAT + tid];
    __syncthreads();
    {   // emb[f] = sum_t nt[t] * W_emb[f, t]
        float e = 0.f;
        const float* we = &W_emb[tid * FEAT];
#pragma unroll
        for (int t = 0; t < FEAT; t++) e = fmaf(nt[t], we[t], e);
        emb[tid] = e;
    }
    __syncthreads();

    // stage h tile (32 x 128) -> hs
    {
        const float4* h4 = (const float4*)(h + (size_t)g * NA * HID);
        for (int idx = tid; idx < 32 * 32; idx += 128) {
            int r = idx >> 5, c4 = idx & 31;
            *(float4*)&hs[r * 132 + c4 * 4] = h4[idx];
        }
    }
    // stage W slice (64 x 128) ⊙ emb -> Wsh
    const int gc0 = s * 64;
    {
        const float4* w4 = (const float4*)(W_qkv + (size_t)gc0 * HID);
        for (int idx = tid; idx < 64 * 32; idx += 128) {
            int c = idx >> 5, k4 = idx & 31;
            float4 w = w4[idx];
            float4 e = *(const float4*)&emb[k4 * 4];
            w.x *= e.x; w.y *= e.y; w.z *= e.z; w.w *= e.w;
            *(float4*)&Wsh[c * 132 + k4 * 4] = w;
        }
    }
    __syncthreads();

    const int rt = tid >> 4, ct = tid & 15;       // 8 row-tiles x 16 col-tiles
    const int r0 = rt * 4, c0 = ct * 4;

    unsigned long long acc[4][4];
#pragma unroll
    for (int i = 0; i < 4; i++)
#pragma unroll
        for (int j = 0; j < 4; j++) acc[i][j] = 0ull;

    for (int k4 = 0; k4 < 32; k4++) {
        ulonglong2 a[4], w[4];
#pragma unroll
        for (int i = 0; i < 4; i++) a[i] = *(const ulonglong2*)&hs[(r0 + i) * 132 + k4 * 4];
#pragma unroll
        for (int j = 0; j < 4; j++) w[j] = *(const ulonglong2*)&Wsh[(c0 + j) * 132 + k4 * 4];
#pragma unroll
        for (int i = 0; i < 4; i++)
#pragma unroll
            for (int j = 0; j < 4; j++) {
                fma2(acc[i][j], a[i].x, w[j].x);
                fma2(acc[i][j], a[i].y, w[j].y);
            }
    }

    const int row0 = g * NA + r0;
#pragma unroll
    for (int j = 0; j < 4; j++) {
        float b = b_qkv[gc0 + c0 + j];
#pragma unroll
        for (int i = 0; i < 4; i++)
            g_qkv[(row0 + i) * 384 + gc0 + c0 + j] = hsum2(acc[i][j]) + b;
    }
}

// ---------------------------------------------------------------------------
// K_attn: per-graph 32x32 attention.  grid 64, 256 threads, dynamic smem.
// logits = (q·k^T)/sqrt(32) + t(d)   [per-row bias cancels in softmax]
// vals = (softmax(logits) @ v) * sigmoid(x·W_g + b_g) + x
// ---------------------------------------------------------------------------
__global__ void k_attn(const float* __restrict__ h,
                       const float* __restrict__ pos,
                       const float* __restrict__ next_type,
                       const float* __restrict__ W_emb,
                       const float* __restrict__ W_g,
                       const float* __restrict__ b_g,
                       const float* __restrict__ W_t,
                       const float* __restrict__ b_t) {
    extern __shared__ float sm[];
    float* xs  = sm;                 // 32*132
    float* qs  = xs + 32 * 132;      // 32*132
    float* ks  = qs + 32 * 132;      // 32*132
    float* vs  = ks + 32 * 132;      // 32*132
    float* att = vs + 32 * 132;      // 32*33
    float* px  = att + 32 * 33;      // 32
    float* py  = px + 32;            // 32
    float* pz  = py + 32;            // 32
    float* gs  = pz + 32;            // 32
    float* wt  = gs + 32;            // 32
    float* nt  = wt + 32;            // 64
    float* emb = nt + 64;            // 128

    const int g = blockIdx.x, tid = threadIdx.x;
    if (tid < FEAT) nt[tid] = next_type[g * FEAT + tid];
    else if (tid >= 64 && tid < 96) {
        int i = tid - 64;
        px[i] = pos[(g * NA + i) * 3 + 0];
        py[i] = pos[(g * NA + i) * 3 + 1];
        pz[i] = pos[(g * NA + i) * 3 + 2];
    } else if (tid >= 96 && tid < 128) {
        wt[tid - 96] = W_t[tid - 96];
    }
    __syncthreads();
    if (tid < HID) {
        float e = 0.f;
        const float* we = &W_emb[tid * FEAT];
#pragma unroll
        for (int t = 0; t < FEAT; t++) e = fmaf(nt[t], we[t], e);
        emb[tid] = e;
    }
    __syncthreads();

    // xs = h * emb : thread = (feature, row-half)
    {
        const int f = tid & 127, ih = tid >> 7;
        const float e = emb[f];
#pragma unroll
        for (int i = ih * 16; i < ih * 16 + 16; i++)
            xs[i * 132 + f] = h[(g * NA + i) * HID + f] * e;
    }

    // load q/k/v slices from g_qkv
    const float4* q4 = (const float4*)g_qkv;
    for (int idx = tid; idx < NA * 96; idx += 256) {
        int row = idx / 96, c4 = idx - row * 96;
        float4 v = q4[(g * NA + row) * 96 + c4];
        int c = c4 * 4;
        float* dst = (c < 128) ? &qs[row * 132 + c]
                   : (c < 256) ? &ks[row * 132 + c - 128]
                               : &vs[row * 132 + c - 256];
        *(float4*)dst = v;
    }
    __syncthreads();

    // gate: 8 threads per row, shfl-combine
    {
        int i = tid >> 3, part = tid & 7;
        float a = 0.f;
#pragma unroll
        for (int t = 0; t < 16; t++) {
            int k = part * 16 + t;
            a = fmaf(xs[i * 132 + k], __ldg(&W_g[k]), a);
        }
        a += __shfl_xor_sync(0xffffffffu, a, 1);
        a += __shfl_xor_sync(0xffffffffu, a, 2);
        a += __shfl_xor_sync(0xffffffffu, a, 4);
        if (part == 0) gs[i] = 1.f / (1.f + __expf(-(a + b_g[0])));
    }

    // logits: 4 pairs/thread
    const float RS = 0.17677669529663688f;   // 1/sqrt(32)
    const float bt0 = b_t[0];
#pragma unroll
    for (int m = 0; m < 4; m++) {
        int p = tid + 256 * m;
        int i = p >> 5, j = p & 31;
        float dx = px[i] - px[j], dy = py[i] - py[j], dz = pz[i] - pz[j];
        float sq = dx * dx + dy * dy + dz * dz;
        float d  = sqrtf(fmaxf(sq, 1e-12f));
        float t  = bt0;
#pragma unroll
        for (int kk = 0; kk < 32; kk++) {
            float u = d - kk * (10.f / 31.f);
            t = fmaf(wt[kk], __expf(-10.f * u * u), t);
        }
        unsigned long long acc = 0ull;
        const ulonglong2* qq = (const ulonglong2*)&qs[i * 132];
        const ulonglong2* kp = (const ulonglong2*)&ks[j * 132];
#pragma unroll 8
        for (int k4 = 0; k4 < 32; k4++) {
            ulonglong2 a = qq[k4], b = kp[k4];
            fma2(acc, a.x, b.x);
            fma2(acc, a.y, b.y);
        }
        att[i * 33 + j] = hsum2(acc) * RS + t;
    }
    __syncthreads();

    // softmax: 8 warps x 4 rows
    {
        int w = tid >> 5, lane = tid & 31;
#pragma unroll
        for (int rr = 0; rr < 4; rr++) {
            int r = w * 4 + rr;
            float v = att[r * 33 + lane];
            float mx = v;
#pragma unroll
            for (int o = 16; o > 0; o >>= 1) mx = fmaxf(mx, __shfl_xor_sync(0xffffffffu, mx, o));
            float e = __expf(v - mx);
            float ss = e;
#pragma unroll
            for (int o = 16; o > 0; o >>= 1) ss += __shfl_xor_sync(0xffffffffu, ss, o);
            att[r * 33 + lane] = e / ss;
        }
    }
    __syncthreads();

    // out: thread = (feature f, 16-row half)
    {
        const int f = tid & 127, ih = tid >> 7;
        const int i0 = ih * 16;
        float acc[16];
#pragma unroll
        for (int i = 0; i < 16; i++) acc[i] = 0.f;
        for (int j = 0; j < NA; j++) {
            float vj = vs[j * 132 + f];
#pragma unroll
            for (int i = 0; i < 16; i++)
                acc[i] = fmaf(att[(i0 + i) * 33 + j], vj, acc[i]);
        }
#pragma unroll
        for (int i = 0; i < 16; i++)
            g_vals[(g * NA + i0 + i) * HID + f] =
                fmaf(acc[i], gs[i0 + i], xs[(i0 + i) * 132 + f]);
    }
}

// ---------------------------------------------------------------------------
// K_dense: 128 -> SiLU 106 -> SiLU 85 -> 64 -> log_softmax
// grid 128 (16 rows each), 256 threads.
// x-rows staged in smem; W0/W1 read via __ldg (L1-resident after first touch);
// W2 repacked in smem (global rows only 4B-aligned).  f32x2 k-pair FMAs.
// ---------------------------------------------------------------------------
__global__ void k_dense(const float* __restrict__ W_d0, const float* __restrict__ b_d0,
                        const float* __restrict__ W_d1, const float* __restrict__ b_d1,
                        const float* __restrict__ W_d2, const float* __restrict__ b_d2,
                        float* __restrict__ out) {
    extern __shared__ float sm[];
    float* xs = sm;                  // 16*132 = 2112
    float* y0 = xs + 16 * 132;       // 16*108 = 1728
    float* y1 = y0 + 16 * 108;       // 16*88  = 1408
    float* y2 = y1 + 16 * 88;        // 16*66  = 1056
    float* W2 = y2 + 16 * 66;        // 64*88  = 5632   (total 11936 floats)

    const int tid  = threadIdx.x;
    const int row0 = blockIdx.x * 16;

    // stage x rows
    {
        const float4* v4 = (const float4*)(g_vals + (size_t)row0 * HID);
        for (int idx = tid; idx < 16 * 32; idx += 256) {
            int r = idx >> 5, c4 = idx & 31;
            *(float4*)&xs[r * 132 + c4 * 4] = v4[idx];
        }
    }
    // stage W2 repacked to stride 88
    for (int idx = tid; idx < 64 * 85; idx += 256) {
        int c = idx / 85, k = idx - c * 85;
        W2[c * 88 + k] = __ldg(&W_d2[idx]);
    }
    __syncthreads();

    // layer 0: K=128, 106 outputs
    {
        int c = tid & 127, rg = tid >> 7;
        if (c < 106) {
            unsigned long long acc[8];
#pragma unroll
            for (int r = 0; r < 8; r++) acc[r] = 0ull;
            const ulonglong2* w2p = (const ulonglong2*)(W_d0 + (size_t)c * 128);
            for (int k4 = 0; k4 < 32; k4++) {
                ulonglong2 w = __ldg(&w2p[k4]);
#pragma unroll
                for (int r = 0; r < 8; r++) {
                    ulonglong2 x = *(const ulonglong2*)&xs[(rg * 8 + r) * 132 + k4 * 4];
                    fma2(acc[r], x.x, w.x);
                    fma2(acc[r], x.y, w.y);
                }
            }
            float b = __ldg(&b_d0[c]);
#pragma unroll
            for (int r = 0; r < 8; r++) {
                float z = hsum2(acc[r]) + b;
                y0[(rg * 8 + r) * 108 + c] = z / (1.f + __expf(-z));
            }
        }
    }
    __syncthreads();

    // layer 1: K=106 (53 u64 pairs; rows 8B-aligned), 85 outputs
    {
        int c = tid & 127, rg = tid >> 7;
        if (c < 85) {
            unsigned long long acc[8];
#pragma unroll
            for (int r = 0; r < 8; r++) acc[r] = 0ull;
            const unsigned long long* wp = (const unsigned long long*)(W_d1 + (size_t)c * 106);
            for (int k2 = 0; k2 < 53; k2++) {
                unsigned long long w = __ldg(&wp[k2]);
#pragma unroll
                for (int r = 0; r < 8; r++) {
                    unsigned long long x = *(const unsigned long long*)&y0[(rg * 8 + r) * 108 + k2 * 2];
                    fma2(acc[r], x, w);
                }
            }
            float b = __ldg(&b_d1[c]);
#pragma unroll
            for (int r = 0; r < 8; r++) {
                float z = hsum2(acc[r]) + b;
                y1[(rg * 8 + r) * 88 + c] = z / (1.f + __expf(-z));
            }
        }
    }
    __syncthreads();

    // layer 2: K=85 (42 pairs + 1 scalar), 64 outputs, 4 rows/thread
    {
        int c = tid & 63, rg = tid >> 6;
        unsigned long long acc[4];
#pragma unroll
        for (int r = 0; r < 4; r++) acc[r] = 0ull;
        const unsigned long long* wp = (const unsigned long long*)&W2[c * 88];
        for (int k2 = 0; k2 < 42; k2++) {
            unsigned long long w = wp[k2];
#pragma unroll
            for (int r = 0; r < 4; r++) {
                unsigned long long x = *(const unsigned long long*)&y1[(rg * 4 + r) * 88 + k2 * 2];
                fma2(acc[r], x, w);
            }
        }
        float b = __ldg(&b_d2[c]);
        float wl = W2[c * 88 + 84];
#pragma unroll
        for (int r = 0; r < 4; r++) {
            float z = hsum2(acc[r]) + fmaf(y1[(rg * 4 + r) * 88 + 84], wl, b);
            y2[(rg * 4 + r) * 66 + c] = z;
        }
    }
    __syncthreads();

    // log_softmax over 64: 8 warps x 2 rows
    {
        int w = tid >> 5, lane = tid & 31;
#pragma unroll
        for (int rr = 0; rr < 2; rr++) {
            int r = w * 2 + rr;
            float e0 = y2[r * 66 + lane], e1 = y2[r * 66 + lane + 32];
            float mx = fmaxf(e0, e1);
#pragma unroll
            for (int o = 16; o > 0; o >>= 1) mx = fmaxf(mx, __shfl_xor_sync(0xffffffffu, mx, o));
            float s = __expf(e0 - mx) + __expf(e1 - mx);
#pragma unroll
            for (int o = 16; o > 0; o >>= 1) s += __shfl_xor_sync(0xffffffffu, s, o);
            float l = mx + __logf(s);
            out[(row0 + r) * 64 + lane]      = e0 - l;
            out[(row0 + r) * 64 + lane + 32] = e1 - l;
        }
    }
}

// ---------------------------------------------------------------------------
extern "C" void kernel_launch(void* const* d_in, const int* in_sizes, int n_in,
                              void* d_out, int out_size) {
    const float* h         = (const float*)d_in[0];
    const float* pos       = (const float*)d_in[1];
    const float* next_type = (const float*)d_in[2];
    // d_in[3] = batch (int32) — structure fixed (arange//32), unused
    const float* W_emb = (const float*)d_in[4];
    const float* W_qkv = (const float*)d_in[5];
    const float* b_qkv = (const float*)d_in[6];
    // d_in[7] W_b, d_in[8] b_b — per-row bias cancels inside softmax, unused
    const float* W_g  = (const float*)d_in[9];
    const float* b_g  = (const float*)d_in[10];
    const float* W_t  = (const float*)d_in[11];
    const float* b_t  = (const float*)d_in[12];
    const float* W_d0 = (const float*)d_in[13];
    const float* b_d0 = (const float*)d_in[14];
    const float* W_d1 = (const float*)d_in[15];
    const float* b_d1 = (const float*)d_in[16];
    const float* W_d2 = (const float*)d_in[17];
    const float* b_d2 = (const float*)d_in[18];
    float* out = (float*)d_out;

    const int smem_attn  = 18304 * 4;   // 73216 B
    const int smem_dense = 11936 * 4;   // 47744 B
    static int configured = 0;
    cudaFuncSetAttribute(k_attn,  cudaFuncAttributeMaxDynamicSharedMemorySize, smem_attn);
    cudaFuncSetAttribute(k_dense, cudaFuncAttributeMaxDynamicSharedMemorySize, smem_dense);
    (void)configured;

    k_qkv<<<dim3(6, 64), 128>>>(h, next_type, W_emb, W_qkv, b_qkv);
    k_attn<<<64, 256, smem_attn>>>(h, pos, next_type, W_emb, W_g, b_g, W_t, b_t);
    k_dense<<<128, 256, smem_dense>>>(W_d0, b_d0, W_d1, b_d1, W_d2, b_d2, out);
}

// round 6
// speedup vs baseline: 1.4294x; 1.1776x over previous
#include <cuda_runtime.h>

#define NG   64
#define NA   32
#define NN   2048
#define HID  128
#define FEAT 64

// scratch (static device globals — no runtime allocation)
__device__ __align__(16) float g_qkv[NN * 384];
__device__ __align__(16) float g_vals[NN * HID];

// packed f32x2 FMA: acc.{lo,hi} += a.{lo,hi} * b.{lo,hi}
__device__ __forceinline__ void fma2(unsigned long long& acc,
                                     unsigned long long a,
                                     unsigned long long b) {
    asm("fma.rn.f32x2 %0, %1, %2, %0;" : "+l"(acc) : "l"(a), "l"(b));
}
__device__ __forceinline__ float hsum2(unsigned long long a) {
    float lo = __uint_as_float((unsigned)(a & 0xffffffffull));
    float hi = __uint_as_float((unsigned)(a >> 32));
    return lo + hi;
}

// ---------------------------------------------------------------------------
// K_qkv: g_qkv[row, 0:384] = (h ⊙ emb[graph]) @ W_qkv^T + b_qkv
// grid (6 col-slices, 64 graphs), 128 threads.  4 rows x 4 cols per thread;
// thread ct owns cols {ct, ct+16, ct+32, ct+48}: per-j bank group
// (ct + k4) mod 8 -> conflict-free LDS.128.
// ---------------------------------------------------------------------------
__global__ void k_qkv(const float* __restrict__ h,
                      const float* __restrict__ next_type,
                      const float* __restrict__ W_emb,
                      const float* __restrict__ W_qkv,
                      const float* __restrict__ b_qkv) {
    __shared__ float nt[FEAT];
    __shared__ float emb[HID];
    __shared__ __align__(16) float hs[32 * 132];
    __shared__ __align__(16) float Wsh[64 * 132];

    const int g = blockIdx.y, s = blockIdx.x, tid = threadIdx.x;
    if (tid < FEAT) nt[tid] = next_type[g * FEAT + tid];
    __syncthreads();
    {   // emb[f] = sum_t nt[t] * W_emb[f, t]
        float e = 0.f;
        const float* we = &W_emb[tid * FEAT];
#pragma unroll
        for (int t = 0; t < FEAT; t++) e = fmaf(nt[t], we[t], e);
        emb[tid] = e;
    }
    __syncthreads();

    {   // stage h tile (32 x 128)
        const float4* h4 = (const float4*)(h + (size_t)g * NA * HID);
        for (int idx = tid; idx < 32 * 32; idx += 128) {
            int r = idx >> 5, c4 = idx & 31;
            *(float4*)&hs[r * 132 + c4 * 4] = h4[idx];
        }
    }
    const int gc0 = s * 64;
    {   // stage W slice (64 x 128) ⊙ emb
        const float4* w4 = (const float4*)(W_qkv + (size_t)gc0 * HID);
        for (int idx = tid; idx < 64 * 32; idx += 128) {
            int c = idx >> 5, k4 = idx & 31;
            float4 w = w4[idx];
            float4 e = *(const float4*)&emb[k4 * 4];
            w.x *= e.x; w.y *= e.y; w.z *= e.z; w.w *= e.w;
            *(float4*)&Wsh[c * 132 + k4 * 4] = w;
        }
    }
    __syncthreads();

    const int rt = tid >> 4, ct = tid & 15;       // 8 row-tiles x 16 col-threads
    const int r0 = rt * 4;

    unsigned long long acc[4][4];
#pragma unroll
    for (int i = 0; i < 4; i++)
#pragma unroll
        for (int j = 0; j < 4; j++) acc[i][j] = 0ull;

#pragma unroll 2
    for (int k4 = 0; k4 < 32; k4++) {
        ulonglong2 a[4], w[4];
#pragma unroll
        for (int i = 0; i < 4; i++) a[i] = *(const ulonglong2*)&hs[(r0 + i) * 132 + k4 * 4];
#pragma unroll
        for (int j = 0; j < 4; j++) w[j] = *(const ulonglong2*)&Wsh[(ct + 16 * j) * 132 + k4 * 4];
#pragma unroll
        for (int i = 0; i < 4; i++)
#pragma unroll
            for (int j = 0; j < 4; j++) {
                fma2(acc[i][j], a[i].x, w[j].x);
                fma2(acc[i][j], a[i].y, w[j].y);
            }
    }

    const int row0 = g * NA + r0;
#pragma unroll
    for (int j = 0; j < 4; j++) {
        const int gc = gc0 + ct + 16 * j;
        float b = b_qkv[gc];
#pragma unroll
        for (int i = 0; i < 4; i++)
            g_qkv[(row0 + i) * 384 + gc] = hsum2(acc[i][j]) + b;
    }
}

// ---------------------------------------------------------------------------
// K_attn: per-graph 32x32 attention.  grid 64, 256 threads, dynamic smem.
// logits loop: j uniform per warp (k-row broadcast), i = lane (conflict-free).
// ---------------------------------------------------------------------------
__global__ void k_attn(const float* __restrict__ h,
                       const float* __restrict__ pos,
                       const float* __restrict__ next_type,
                       const float* __restrict__ W_emb,
                       const float* __restrict__ W_g,
                       const float* __restrict__ b_g,
                       const float* __restrict__ W_t,
                       const float* __restrict__ b_t) {
    extern __shared__ __align__(16) float sm[];
    float* xs  = sm;                 // 32*132  (16B: 132*4=528 ÷16)
    float* qs  = xs + 32 * 132;      // 32*132
    float* ks  = qs + 32 * 132;      // 32*132
    float* vs  = ks + 32 * 132;      // 32*132
    float* att = vs + 32 * 132;      // 32*33
    float* px  = att + 32 * 33;      // 32
    float* py  = px + 32;            // 32
    float* pz  = py + 32;            // 32
    float* gs  = pz + 32;            // 32
    float* wt  = gs + 32;            // 32
    float* nt  = wt + 32;            // 64
    float* emb = nt + 64;            // 128

    const int g = blockIdx.x, tid = threadIdx.x;
    if (tid < FEAT) nt[tid] = next_type[g * FEAT + tid];
    else if (tid >= 64 && tid < 96) {
        int i = tid - 64;
        px[i] = pos[(g * NA + i) * 3 + 0];
        py[i] = pos[(g * NA + i) * 3 + 1];
        pz[i] = pos[(g * NA + i) * 3 + 2];
    } else if (tid >= 96 && tid < 128) {
        wt[tid - 96] = W_t[tid - 96];
    }
    __syncthreads();
    if (tid < HID) {
        float e = 0.f;
        const float* we = &W_emb[tid * FEAT];
#pragma unroll
        for (int t = 0; t < FEAT; t++) e = fmaf(nt[t], we[t], e);
        emb[tid] = e;
    }
    __syncthreads();

    // xs = h * emb : thread = (feature, row-half)
    {
        const int f = tid & 127, ih = tid >> 7;
        const float e = emb[f];
#pragma unroll
        for (int i = ih * 16; i < ih * 16 + 16; i++)
            xs[i * 132 + f] = h[(g * NA + i) * HID + f] * e;
    }

    // load q/k/v slices from g_qkv
    const float4* q4 = (const float4*)g_qkv;
    for (int idx = tid; idx < NA * 96; idx += 256) {
        int row = idx / 96, c4 = idx - row * 96;
        float4 v = q4[(g * NA + row) * 96 + c4];
        int c = c4 * 4;
        float* dst = (c < 128) ? &qs[row * 132 + c]
                   : (c < 256) ? &ks[row * 132 + c - 128]
                               : &vs[row * 132 + c - 256];
        *(float4*)dst = v;
    }
    __syncthreads();

    // gate: 8 threads per row, shfl-combine
    {
        int i = tid >> 3, part = tid & 7;
        float a = 0.f;
#pragma unroll
        for (int t = 0; t < 16; t++) {
            int k = part * 16 + t;
            a = fmaf(xs[i * 132 + k], __ldg(&W_g[k]), a);
        }
        a += __shfl_xor_sync(0xffffffffu, a, 1);
        a += __shfl_xor_sync(0xffffffffu, a, 2);
        a += __shfl_xor_sync(0xffffffffu, a, 4);
        if (part == 0) gs[i] = 1.f / (1.f + __expf(-(a + b_g[0])));
    }

    // logits: 4 pairs/thread; j uniform per warp, i = lane
    const float RS = 0.17677669529663688f;   // 1/sqrt(32)
    const float bt0 = b_t[0];
#pragma unroll
    for (int m = 0; m < 4; m++) {
        int p = tid + 256 * m;
        int j = p >> 5, i = p & 31;
        float dx = px[i] - px[j], dy = py[i] - py[j], dz = pz[i] - pz[j];
        float sq = dx * dx + dy * dy + dz * dz;
        float d  = sqrtf(fmaxf(sq, 1e-12f));
        float t  = bt0;
#pragma unroll
        for (int kk = 0; kk < 32; kk++) {
            float u = d - kk * (10.f / 31.f);
            t = fmaf(wt[kk], __expf(-10.f * u * u), t);
        }
        unsigned long long acc = 0ull;
        const ulonglong2* qq = (const ulonglong2*)&qs[i * 132];
        const ulonglong2* kp = (const ulonglong2*)&ks[j * 132];
#pragma unroll 8
        for (int k4 = 0; k4 < 32; k4++) {
            ulonglong2 a = qq[k4], b = kp[k4];
            fma2(acc, a.x, b.x);
            fma2(acc, a.y, b.y);
        }
        att[i * 33 + j] = hsum2(acc) * RS + t;
    }
    __syncthreads();

    // softmax: 8 warps x 4 rows
    {
        int w = tid >> 5, lane = tid & 31;
#pragma unroll
        for (int rr = 0; rr < 4; rr++) {
            int r = w * 4 + rr;
            float v = att[r * 33 + lane];
            float mx = v;
#pragma unroll
            for (int o = 16; o > 0; o >>= 1) mx = fmaxf(mx, __shfl_xor_sync(0xffffffffu, mx, o));
            float e = __expf(v - mx);
            float ss = e;
#pragma unroll
            for (int o = 16; o > 0; o >>= 1) ss += __shfl_xor_sync(0xffffffffu, ss, o);
            att[r * 33 + lane] = e / ss;
        }
    }
    __syncthreads();

    // out: thread = (feature f, 16-row half)
    {
        const int f = tid & 127, ih = tid >> 7;
        const int i0 = ih * 16;
        float acc[16];
#pragma unroll
        for (int i = 0; i < 16; i++) acc[i] = 0.f;
        for (int j = 0; j < NA; j++) {
            float vj = vs[j * 132 + f];
#pragma unroll
            for (int i = 0; i < 16; i++)
                acc[i] = fmaf(att[(i0 + i) * 33 + j], vj, acc[i]);
        }
#pragma unroll
        for (int i = 0; i < 16; i++)
            g_vals[(g * NA + i0 + i) * HID + f] =
                fmaf(acc[i], gs[i0 + i], xs[(i0 + i) * 132 + f]);
    }
}

// ---------------------------------------------------------------------------
// K_dense: 128 -> SiLU 106 -> SiLU 85 -> 64 -> log_softmax
// grid 128 (16 rows each), 256 threads.
// smem layout ordered so every float4/u128 consumer is 16B-aligned:
//   xs @0 (16B), W0 @2112 floats = 8448B (÷16), the rest are u64/scalars (÷8).
// ---------------------------------------------------------------------------
__global__ void k_dense(const float* __restrict__ W_d0, const float* __restrict__ b_d0,
                        const float* __restrict__ W_d1, const float* __restrict__ b_d1,
                        const float* __restrict__ W_d2, const float* __restrict__ b_d2,
                        float* __restrict__ out) {
    extern __shared__ __align__(16) float smd[];
    float* xs = smd;                 // 16*132 = 2112   (float4 + u128: 16B OK)
    float* W0 = xs + 16 * 132;       // 106*132 = 13992 (u128: byte 8448 ÷16 OK)
    float* W1 = W0 + 106 * 132;      // 85*110 = 9350   (u64: byte 64416 ÷8 OK)
    float* W2 = W1 + 85 * 110;       // 64*90  = 5760   (u64: byte 101816 ÷8 OK)
    float* y0 = W2 + 64 * 90;        // 16*108 = 1728   (u64: byte 124856 ÷8 OK)
    float* y1 = y0 + 16 * 108;       // 16*88  = 1408   (u64: byte 131768 ÷8 OK)
    float* y2 = y1 + 16 * 88;        // 16*66  = 1056   (scalar)
                                     // total 35406 floats

    const int tid  = threadIdx.x;
    const int row0 = blockIdx.x * 16;

    // stage x rows (float4)
    {
        const float4* v4 = (const float4*)(g_vals + (size_t)row0 * HID);
        for (int idx = tid; idx < 16 * 32; idx += 256) {
            int r = idx >> 5, c4 = idx & 31;
            *(float4*)&xs[r * 132 + c4 * 4] = v4[idx];
        }
    }
    // stage weights
    {
        const float4* w4 = (const float4*)W_d0;
        for (int idx = tid; idx < 106 * 32; idx += 256) {
            int c = idx >> 5, k4 = idx & 31;
            *(float4*)&W0[c * 132 + k4 * 4] = w4[idx];
        }
    }
    for (int idx = tid; idx < 85 * 106; idx += 256) {
        int c = idx / 106, k = idx - c * 106;
        W1[c * 110 + k] = __ldg(&W_d1[idx]);
    }
    for (int idx = tid; idx < 64 * 85; idx += 256) {
        int c = idx / 85, k = idx - c * 85;
        W2[c * 90 + k] = __ldg(&W_d2[idx]);
    }
    __syncthreads();

    // layer 0: K=128, 106 outputs, 8 rows/thread
    {
        int c = tid & 127, rg = tid >> 7;
        if (c < 106) {
            unsigned long long acc[8];
#pragma unroll
            for (int r = 0; r < 8; r++) acc[r] = 0ull;
#pragma unroll 4
            for (int k4 = 0; k4 < 32; k4++) {
                ulonglong2 w = *(const ulonglong2*)&W0[c * 132 + k4 * 4];
#pragma unroll
                for (int r = 0; r < 8; r++) {
                    ulonglong2 x = *(const ulonglong2*)&xs[(rg * 8 + r) * 132 + k4 * 4];
                    fma2(acc[r], x.x, w.x);
                    fma2(acc[r], x.y, w.y);
                }
            }
            float b = __ldg(&b_d0[c]);
#pragma unroll
            for (int r = 0; r < 8; r++) {
                float z = hsum2(acc[r]) + b;
                y0[(rg * 8 + r) * 108 + c] = z / (1.f + __expf(-z));
            }
        }
    }
    __syncthreads();

    // layer 1: K=106 (53 u64 pairs), 85 outputs
    {
        int c = tid & 127, rg = tid >> 7;
        if (c < 85) {
            unsigned long long acc[8];
#pragma unroll
            for (int r = 0; r < 8; r++) acc[r] = 0ull;
            const unsigned long long* wp = (const unsigned long long*)&W1[c * 110];
#pragma unroll 4
            for (int k2 = 0; k2 < 53; k2++) {
                unsigned long long w = wp[k2];
#pragma unroll
                for (int r = 0; r < 8; r++) {
                    unsigned long long x = *(const unsigned long long*)&y0[(rg * 8 + r) * 108 + k2 * 2];
                    fma2(acc[r], x, w);
                }
            }
            float b = __ldg(&b_d1[c]);
#pragma unroll
            for (int r = 0; r < 8; r++) {
                float z = hsum2(acc[r]) + b;
                y1[(rg * 8 + r) * 88 + c] = z / (1.f + __expf(-z));
            }
        }
    }
    __syncthreads();

    // layer 2: K=85 (42 pairs + 1 scalar), 64 outputs, 4 rows/thread
    {
        int c = tid & 63, rg = tid >> 6;
        unsigned long long acc[4];
#pragma unroll
        for (int r = 0; r < 4; r++) acc[r] = 0ull;
        const unsigned long long* wp = (const unsigned long long*)&W2[c * 90];
#pragma unroll 4
        for (int k2 = 0; k2 < 42; k2++) {
            unsigned long long w = wp[k2];
#pragma unroll
            for (int r = 0; r < 4; r++) {
                unsigned long long x = *(const unsigned long long*)&y1[(rg * 4 + r) * 88 + k2 * 2];
                fma2(acc[r], x, w);
            }
        }
        float b = __ldg(&b_d2[c]);
        float wl = W2[c * 90 + 84];
#pragma unroll
        for (int r = 0; r < 4; r++) {
            float z = hsum2(acc[r]) + fmaf(y1[(rg * 4 + r) * 88 + 84], wl, b);
            y2[(rg * 4 + r) * 66 + c] = z;
        }
    }
    __syncthreads();

    // log_softmax over 64: 8 warps x 2 rows
    {
        int w = tid >> 5, lane = tid & 31;
#pragma unroll
        for (int rr = 0; rr < 2; rr++) {
            int r = w * 2 + rr;
            float e0 = y2[r * 66 + lane], e1 = y2[r * 66 + lane + 32];
            float mx = fmaxf(e0, e1);
#pragma unroll
            for (int o = 16; o > 0; o >>= 1) mx = fmaxf(mx, __shfl_xor_sync(0xffffffffu, mx, o));
            float s = __expf(e0 - mx) + __expf(e1 - mx);
#pragma unroll
            for (int o = 16; o > 0; o >>= 1) s += __shfl_xor_sync(0xffffffffu, s, o);
            float l = mx + __logf(s);
            out[(row0 + r) * 64 + lane]      = e0 - l;
            out[(row0 + r) * 64 + lane + 32] = e1 - l;
        }
    }
}

// ---------------------------------------------------------------------------
extern "C" void kernel_launch(void* const* d_in, const int* in_sizes, int n_in,
                              void* d_out, int out_size) {
    const float* h         = (const float*)d_in[0];
    const float* pos       = (const float*)d_in[1];
    const float* next_type = (const float*)d_in[2];
    // d_in[3] = batch (int32) — structure fixed (arange//32), unused
    const float* W_emb = (const float*)d_in[4];
    const float* W_qkv = (const float*)d_in[5];
    const float* b_qkv = (const float*)d_in[6];
    // d_in[7] W_b, d_in[8] b_b — per-row bias cancels inside softmax, unused
    const float* W_g  = (const float*)d_in[9];
    const float* b_g  = (const float*)d_in[10];
    const float* W_t  = (const float*)d_in[11];
    const float* b_t  = (const float*)d_in[12];
    const float* W_d0 = (const float*)d_in[13];
    const float* b_d0 = (const float*)d_in[14];
    const float* W_d1 = (const float*)d_in[15];
    const float* b_d1 = (const float*)d_in[16];
    const float* W_d2 = (const float*)d_in[17];
    const float* b_d2 = (const float*)d_in[18];
    float* out = (float*)d_out;

    const int smem_attn  = 18304 * 4;   // 73216 B
    const int smem_dense = 35406 * 4;   // 141624 B
    cudaFuncSetAttribute(k_attn,  cudaFuncAttributeMaxDynamicSharedMemorySize, smem_attn);
    cudaFuncSetAttribute(k_dense, cudaFuncAttributeMaxDynamicSharedMemorySize, smem_dense);

    k_qkv<<<dim3(6, 64), 128>>>(h, next_type, W_emb, W_qkv, b_qkv);
    k_attn<<<64, 256, smem_attn>>>(h, pos, next_type, W_emb, W_g, b_g, W_t, b_t);
    k_dense<<<128, 256, smem_dense>>>(W_d0, b_d0, W_d1, b_d1, W_d2, b_d2, out);
}

// round 12
// speedup vs baseline: 1.8267x; 1.2779x over previous
#include <cuda_runtime.h>

#define NG   64
#define NA   32
#define NN   2048
#define HID  128
#define FEAT 64

// scratch (static device globals — no runtime allocation)
__device__ __align__(16) float g_qkv[NN * 384];
__device__ __align__(16) float g_vals[NN * HID];
__device__ __align__(16) float g_emb[NG * HID];

// packed f32x2 FMA: acc.{lo,hi} += a.{lo,hi} * b.{lo,hi}
__device__ __forceinline__ void fma2(unsigned long long& acc,
                                     unsigned long long a,
                                     unsigned long long b) {
    asm("fma.rn.f32x2 %0, %1, %2, %0;" : "+l"(acc) : "l"(a), "l"(b));
}
__device__ __forceinline__ float hsum2(unsigned long long a) {
    float lo = __uint_as_float((unsigned)(a & 0xffffffffull));
    float hi = __uint_as_float((unsigned)(a >> 32));
    return lo + hi;
}

// ---------------------------------------------------------------------------
// K_emb: g_emb[g, f] = sum_t next_type[g,t] * W_emb[f,t]
// grid 64, 128 threads.  W_emb staged TRANSPOSED (stride 129) so the compute
// loop reads consecutive-lane, conflict-free smem.
// ---------------------------------------------------------------------------
__global__ void k_emb(const float* __restrict__ next_type,
                      const float* __restrict__ W_emb) {
    __shared__ float nt[FEAT];
    __shared__ float weT[FEAT * 129];   // [t][f], stride 129

    const int g = blockIdx.x, tid = threadIdx.x;
    if (tid < FEAT) nt[tid] = next_type[g * FEAT + tid];

    // transpose-stage W_emb (128 rows x 64 cols, row-major) -> weT[t][f]
    const float4* w4 = (const float4*)W_emb;
#pragma unroll
    for (int it = 0; it < 16; it++) {
        int idx = tid + 128 * it;            // over 2048 float4s
        int f = idx >> 4, t4 = idx & 15;
        float4 w = w4[idx];
        weT[(t4 * 4 + 0) * 129 + f] = w.x;
        weT[(t4 * 4 + 1) * 129 + f] = w.y;
        weT[(t4 * 4 + 2) * 129 + f] = w.z;
        weT[(t4 * 4 + 3) * 129 + f] = w.w;
    }
    __syncthreads();

    float e = 0.f;
#pragma unroll
    for (int t = 0; t < FEAT; t++)
        e = fmaf(nt[t], weT[t * 129 + tid], e);
    g_emb[g * HID + tid] = e;
}

// ---------------------------------------------------------------------------
// K_qkv: g_qkv[row, 0:384] = (h ⊙ emb[graph]) @ W_qkv^T + b_qkv
// grid (6 col-slices, 64 graphs), 128 threads.  4 rows x 4 cols per thread;
// thread ct owns cols {ct, ct+16, ct+32, ct+48}: conflict-free LDS.128.
// ---------------------------------------------------------------------------
__global__ void k_qkv(const float* __restrict__ h,
                      const float* __restrict__ W_qkv,
                      const float* __restrict__ b_qkv) {
    __shared__ __align__(16) float emb[HID];
    __shared__ __align__(16) float hs[32 * 132];
    __shared__ __align__(16) float Wsh[64 * 132];

    const int g = blockIdx.y, s = blockIdx.x, tid = threadIdx.x;
    if (tid < 32)
        ((float4*)emb)[tid] = ((const float4*)(g_emb + g * HID))[tid];
    __syncthreads();

    {   // stage h tile (32 x 128)
        const float4* h4 = (const float4*)(h + (size_t)g * NA * HID);
        for (int idx = tid; idx < 32 * 32; idx += 128) {
            int r = idx >> 5, c4 = idx & 31;
            *(float4*)&hs[r * 132 + c4 * 4] = h4[idx];
        }
    }
    const int gc0 = s * 64;
    {   // stage W slice (64 x 128) ⊙ emb
        const float4* w4 = (const float4*)(W_qkv + (size_t)gc0 * HID);
        for (int idx = tid; idx < 64 * 32; idx += 128) {
            int c = idx >> 5, k4 = idx & 31;
            float4 w = w4[idx];
            float4 e = *(const float4*)&emb[k4 * 4];
            w.x *= e.x; w.y *= e.y; w.z *= e.z; w.w *= e.w;
            *(float4*)&Wsh[c * 132 + k4 * 4] = w;
        }
    }
    __syncthreads();

    const int rt = tid >> 4, ct = tid & 15;       // 8 row-tiles x 16 col-threads
    const int r0 = rt * 4;

    unsigned long long acc[4][4];
#pragma unroll
    for (int i = 0; i < 4; i++)
#pragma unroll
        for (int j = 0; j < 4; j++) acc[i][j] = 0ull;

#pragma unroll 2
    for (int k4 = 0; k4 < 32; k4++) {
        ulonglong2 a[4], w[4];
#pragma unroll
        for (int i = 0; i < 4; i++) a[i] = *(const ulonglong2*)&hs[(r0 + i) * 132 + k4 * 4];
#pragma unroll
        for (int j = 0; j < 4; j++) w[j] = *(const ulonglong2*)&Wsh[(ct + 16 * j) * 132 + k4 * 4];
#pragma unroll
        for (int i = 0; i < 4; i++)
#pragma unroll
            for (int j = 0; j < 4; j++) {
                fma2(acc[i][j], a[i].x, w[j].x);
                fma2(acc[i][j], a[i].y, w[j].y);
            }
    }

    const int row0 = g * NA + r0;
#pragma unroll
    for (int j = 0; j < 4; j++) {
        const int gc = gc0 + ct + 16 * j;
        float b = b_qkv[gc];
#pragma unroll
        for (int i = 0; i < 4; i++)
            g_qkv[(row0 + i) * 384 + gc] = hsum2(acc[i][j]) + b;
    }
}

// ---------------------------------------------------------------------------
// K_attn: per-graph 32x32 attention.  grid 64, 256 threads, dynamic smem.
// logits loop: j uniform per warp (k-row broadcast), i = lane (conflict-free).
// ---------------------------------------------------------------------------
__global__ void k_attn(const float* __restrict__ h,
                       const float* __restrict__ pos,
                       const float* __restrict__ W_g,
                       const float* __restrict__ b_g,
                       const float* __restrict__ W_t,
                       const float* __restrict__ b_t) {
    extern __shared__ __align__(16) float sm[];
    float* xs  = sm;                 // 32*132 = 4224
    float* qs  = xs + 32 * 132;      // 32*132
    float* ks  = qs + 32 * 132;      // 32*132
    float* vs  = ks + 32 * 132;      // 32*132  (subtotal 16896)
    float* att = vs + 32 * 132;      // 32*33 = 1056 (17952)
    float* px  = att + 32 * 33;      // 32
    float* py  = px + 32;            // 32
    float* pz  = py + 32;            // 32
    float* gs  = pz + 32;            // 32
    float* wt  = gs + 32;            // 32   (18112)
    float* wg  = wt + 32;            // 128  (total 18240 floats = 72960 B)

    const int g = blockIdx.x, tid = threadIdx.x;
    if (tid < 32) wt[tid] = W_t[tid];
    else if (tid >= 64 && tid < 96) {
        int i = tid - 64;
        px[i] = pos[(g * NA + i) * 3 + 0];
        py[i] = pos[(g * NA + i) * 3 + 1];
        pz[i] = pos[(g * NA + i) * 3 + 2];
    } else if (tid >= 128) {
        wg[tid - 128] = W_g[tid - 128];
    }

    // xs = h * emb : thread = (feature, row-half)
    {
        const int f = tid & 127, ih = tid >> 7;
        const float e = g_emb[g * HID + f];
#pragma unroll
        for (int i = ih * 16; i < ih * 16 + 16; i++)
            xs[i * 132 + f] = h[(g * NA + i) * HID + f] * e;
    }

    // load q/k/v slices from g_qkv
    const float4* q4 = (const float4*)g_qkv;
    for (int idx = tid; idx < NA * 96; idx += 256) {
        int row = idx / 96, c4 = idx - row * 96;
        float4 v = q4[(g * NA + row) * 96 + c4];
        int c = c4 * 4;
        float* dst = (c < 128) ? &qs[row * 132 + c]
                   : (c < 256) ? &ks[row * 132 + c - 128]
                               : &vs[row * 132 + c - 256];
        *(float4*)dst = v;
    }
    __syncthreads();

    // gate: 8 threads per row, shfl-combine
    {
        int i = tid >> 3, part = tid & 7;
        float a = 0.f;
#pragma unroll
        for (int t = 0; t < 16; t++) {
            int k = part * 16 + t;
            a = fmaf(xs[i * 132 + k], wg[k], a);
        }
        a += __shfl_xor_sync(0xffffffffu, a, 1);
        a += __shfl_xor_sync(0xffffffffu, a, 2);
        a += __shfl_xor_sync(0xffffffffu, a, 4);
        if (part == 0) gs[i] = 1.f / (1.f + __expf(-(a + b_g[0])));
    }

    // logits: 4 pairs/thread; j uniform per warp, i = lane
    const float RS = 0.17677669529663688f;   // 1/sqrt(32)
    const float bt0 = b_t[0];
#pragma unroll
    for (int m = 0; m < 4; m++) {
        int p = tid + 256 * m;
        int j = p >> 5, i = p & 31;
        float dx = px[i] - px[j], dy = py[i] - py[j], dz = pz[i] - pz[j];
        float sq = dx * dx + dy * dy + dz * dz;
        float d  = sqrtf(fmaxf(sq, 1e-12f));
        float t  = bt0;
#pragma unroll
        for (int kk = 0; kk < 32; kk++) {
            float u = d - kk * (10.f / 31.f);
            t = fmaf(wt[kk], __expf(-10.f * u * u), t);
        }
        unsigned long long acc = 0ull;
        const ulonglong2* qq = (const ulonglong2*)&qs[i * 132];
        const ulonglong2* kp = (const ulonglong2*)&ks[j * 132];
#pragma unroll 8
        for (int k4 = 0; k4 < 32; k4++) {
            ulonglong2 a = qq[k4], b = kp[k4];
            fma2(acc, a.x, b.x);
            fma2(acc, a.y, b.y);
        }
        att[i * 33 + j] = hsum2(acc) * RS + t;
    }
    __syncthreads();

    // softmax: 8 warps x 4 rows
    {
        int w = tid >> 5, lane = tid & 31;
#pragma unroll
        for (int rr = 0; rr < 4; rr++) {
            int r = w * 4 + rr;
            float v = att[r * 33 + lane];
            float mx = v;
#pragma unroll
            for (int o = 16; o > 0; o >>= 1) mx = fmaxf(mx, __shfl_xor_sync(0xffffffffu, mx, o));
            float e = __expf(v - mx);
            float ss = e;
#pragma unroll
            for (int o = 16; o > 0; o >>= 1) ss += __shfl_xor_sync(0xffffffffu, ss, o);
            att[r * 33 + lane] = e / ss;
        }
    }
    __syncthreads();

    // out: thread = (feature f, 16-row half)
    {
        const int f = tid & 127, ih = tid >> 7;
        const int i0 = ih * 16;
        float acc[16];
#pragma unroll
        for (int i = 0; i < 16; i++) acc[i] = 0.f;
        for (int j = 0; j < NA; j++) {
            float vj = vs[j * 132 + f];
#pragma unroll
            for (int i = 0; i < 16; i++)
                acc[i] = fmaf(att[(i0 + i) * 33 + j], vj, acc[i]);
        }
#pragma unroll
        for (int i = 0; i < 16; i++)
            g_vals[(g * NA + i0 + i) * HID + f] =
                fmaf(acc[i], gs[i0 + i], xs[(i0 + i) * 132 + f]);
    }
}

// ---------------------------------------------------------------------------
// K_dense: 128 -> SiLU 106 -> SiLU 85 -> 64 -> log_softmax
// grid 128 (16 rows each), 256 threads.
// smem layout ordered so every float4/u128 consumer is 16B-aligned.
// ---------------------------------------------------------------------------
__global__ void k_dense(const float* __restrict__ W_d0, const float* __restrict__ b_d0,
                        const float* __restrict__ W_d1, const float* __restrict__ b_d1,
                        const float* __restrict__ W_d2, const float* __restrict__ b_d2,
                        float* __restrict__ out) {
    extern __shared__ __align__(16) float smd[];
    float* xs = smd;                 // 16*132 = 2112   (float4 + u128: 16B OK)
    float* W0 = xs + 16 * 132;       // 106*132 = 13992 (u128: byte 8448 ÷16 OK)
    float* W1 = W0 + 106 * 132;      // 85*110 = 9350   (u64 ÷8 OK)
    float* W2 = W1 + 85 * 110;       // 64*90  = 5760   (u64 ÷8 OK)
    float* y0 = W2 + 64 * 90;        // 16*108 = 1728   (u64 ÷8 OK)
    float* y1 = y0 + 16 * 108;       // 16*88  = 1408   (u64 ÷8 OK)
    float* y2 = y1 + 16 * 88;        // 16*66  = 1056   (scalar)
                                     // total 35406 floats

    const int tid  = threadIdx.x;
    const int row0 = blockIdx.x * 16;

    // stage x rows (float4)
    {
        const float4* v4 = (const float4*)(g_vals + (size_t)row0 * HID);
        for (int idx = tid; idx < 16 * 32; idx += 256) {
            int r = idx >> 5, c4 = idx & 31;
            *(float4*)&xs[r * 132 + c4 * 4] = v4[idx];
        }
    }
    // stage weights
    {
        const float4* w4 = (const float4*)W_d0;
        for (int idx = tid; idx < 106 * 32; idx += 256) {
            int c = idx >> 5, k4 = idx & 31;
            *(float4*)&W0[c * 132 + k4 * 4] = w4[idx];
        }
    }
    for (int idx = tid; idx < 85 * 106; idx += 256) {
        int c = idx / 106, k = idx - c * 106;
        W1[c * 110 + k] = __ldg(&W_d1[idx]);
    }
    for (int idx = tid; idx < 64 * 85; idx += 256) {
        int c = idx / 85, k = idx - c * 85;
        W2[c * 90 + k] = __ldg(&W_d2[idx]);
    }
    __syncthreads();

    // layer 0: K=128, 106 outputs, 8 rows/thread
    {
        int c = tid & 127, rg = tid >> 7;
        if (c < 106) {
            unsigned long long acc[8];
#pragma unroll
            for (int r = 0; r < 8; r++) acc[r] = 0ull;
#pragma unroll 4
            for (int k4 = 0; k4 < 32; k4++) {
                ulonglong2 w = *(const ulonglong2*)&W0[c * 132 + k4 * 4];
#pragma unroll
                for (int r = 0; r < 8; r++) {
                    ulonglong2 x = *(const ulonglong2*)&xs[(rg * 8 + r) * 132 + k4 * 4];
                    fma2(acc[r], x.x, w.x);
                    fma2(acc[r], x.y, w.y);
                }
            }
            float b = __ldg(&b_d0[c]);
#pragma unroll
            for (int r = 0; r < 8; r++) {
                float z = hsum2(acc[r]) + b;
                y0[(rg * 8 + r) * 108 + c] = z / (1.f + __expf(-z));
            }
        }
    }
    __syncthreads();

    // layer 1: K=106 (53 u64 pairs), 85 outputs
    {
        int c = tid & 127, rg = tid >> 7;
        if (c < 85) {
            unsigned long long acc[8];
#pragma unroll
            for (int r = 0; r < 8; r++) acc[r] = 0ull;
            const unsigned long long* wp = (const unsigned long long*)&W1[c * 110];
#pragma unroll 4
            for (int k2 = 0; k2 < 53; k2++) {
                unsigned long long w = wp[k2];
#pragma unroll
                for (int r = 0; r < 8; r++) {
                    unsigned long long x = *(const unsigned long long*)&y0[(rg * 8 + r) * 108 + k2 * 2];
                    fma2(acc[r], x, w);
                }
            }
            float b = __ldg(&b_d1[c]);
#pragma unroll
            for (int r = 0; r < 8; r++) {
                float z = hsum2(acc[r]) + b;
                y1[(rg * 8 + r) * 88 + c] = z / (1.f + __expf(-z));
            }
        }
    }
    __syncthreads();

    // layer 2: K=85 (42 pairs + 1 scalar), 64 outputs, 4 rows/thread
    {
        int c = tid & 63, rg = tid >> 6;
        unsigned long long acc[4];
#pragma unroll
        for (int r = 0; r < 4; r++) acc[r] = 0ull;
        const unsigned long long* wp = (const unsigned long long*)&W2[c * 90];
#pragma unroll 4
        for (int k2 = 0; k2 < 42; k2++) {
            unsigned long long w = wp[k2];
#pragma unroll
            for (int r = 0; r < 4; r++) {
                unsigned long long x = *(const unsigned long long*)&y1[(rg * 4 + r) * 88 + k2 * 2];
                fma2(acc[r], x, w);
            }
        }
        float b = __ldg(&b_d2[c]);
        float wl = W2[c * 90 + 84];
#pragma unroll
        for (int r = 0; r < 4; r++) {
            float z = hsum2(acc[r]) + fmaf(y1[(rg * 4 + r) * 88 + 84], wl, b);
            y2[(rg * 4 + r) * 66 + c] = z;
        }
    }
    __syncthreads();

    // log_softmax over 64: 8 warps x 2 rows
    {
        int w = tid >> 5, lane = tid & 31;
#pragma unroll
        for (int rr = 0; rr < 2; rr++) {
            int r = w * 2 + rr;
            float e0 = y2[r * 66 + lane], e1 = y2[r * 66 + lane + 32];
            float mx = fmaxf(e0, e1);
#pragma unroll
            for (int o = 16; o > 0; o >>= 1) mx = fmaxf(mx, __shfl_xor_sync(0xffffffffu, mx, o));
            float s = __expf(e0 - mx) + __expf(e1 - mx);
#pragma unroll
            for (int o = 16; o > 0; o >>= 1) s += __shfl_xor_sync(0xffffffffu, s, o);
            float l = mx + __logf(s);
            out[(row0 + r) * 64 + lane]      = e0 - l;
            out[(row0 + r) * 64 + lane + 32] = e1 - l;
        }
    }
}

// ---------------------------------------------------------------------------
extern "C" void kernel_launch(void* const* d_in, const int* in_sizes, int n_in,
                              void* d_out, int out_size) {
    const float* h         = (const float*)d_in[0];
    const float* pos       = (const float*)d_in[1];
    const float* next_type = (const float*)d_in[2];
    // d_in[3] = batch (int32) — structure fixed (arange//32), unused
    const float* W_emb = (const float*)d_in[4];
    const float* W_qkv = (const float*)d_in[5];
    const float* b_qkv = (const float*)d_in[6];
    // d_in[7] W_b, d_in[8] b_b — per-row bias cancels inside softmax, unused
    const float* W_g  = (const float*)d_in[9];
    const float* b_g  = (const float*)d_in[10];
    const float* W_t  = (const float*)d_in[11];
    const float* b_t  = (const float*)d_in[12];
    const float* W_d0 = (const float*)d_in[13];
    const float* b_d0 = (const float*)d_in[14];
    const float* W_d1 = (const float*)d_in[15];
    const float* b_d1 = (const float*)d_in[16];
    const float* W_d2 = (const float*)d_in[17];
    const float* b_d2 = (const float*)d_in[18];
    float* out = (float*)d_out;

    const int smem_attn  = 18240 * 4;   // 72960 B  (layout sum verified)
    const int smem_dense = 35406 * 4;   // 141624 B
    cudaFuncSetAttribute(k_attn,  cudaFuncAttributeMaxDynamicSharedMemorySize, smem_attn);
    cudaFuncSetAttribute(k_dense, cudaFuncAttributeMaxDynamicSharedMemorySize, smem_dense);

    k_emb<<<64, 128>>>(next_type, W_emb);
    k_qkv<<<dim3(6, 64), 128>>>(h, W_qkv, b_qkv);
    k_attn<<<64, 256, smem_attn>>>(h, pos, W_g, b_g, W_t, b_t);
    k_dense<<<128, 256, smem_dense>>>(W_d0, b_d0, W_d1, b_d1, W_d2, b_d2, out);
}